// round 3
// baseline (speedup 1.0000x reference)
#include <cuda_runtime.h>

#define BATCH 1024
#define SEQ   512
#define EDIM  300
#define HDIM  512
#define ODIM  5
#define E4    (EDIM / 4)   // 75 float4 slots per row (1200B rows are 16B-aligned)

// Scratch for the pooled embeddings y[B, E] (allocation-free rule: device global)
__device__ __align__(16) float g_y[BATCH * EDIM];

// ---------------------------------------------------------------------------
// Kernel A: per-batch-row embedding gather + sum + length + divide.
// One block per batch row, 96 threads. Threads 0..74 each own one float4 slot
// of the 300-dim embedding, accumulating over all 512 tokens (LDG.128 gathers).
// ---------------------------------------------------------------------------
__global__ __launch_bounds__(96) void gather_mean_kernel(
    const int* __restrict__ x,
    const float* __restrict__ weight)
{
    __shared__ int xs[SEQ];
    __shared__ int firstZero;

    const int b   = blockIdx.x;
    const int tid = threadIdx.x;

    if (tid == 0) firstZero = SEQ;
    __syncthreads();

    const int* xrow = x + b * SEQ;
    for (int l = tid; l < SEQ; l += 96) {
        int t = __ldg(xrow + l);
        xs[l] = t;
        if (t == 0) atomicMin(&firstZero, l);
    }
    __syncthreads();

    // reference semantics: full length if last token nonzero, else first-zero index
    const float len = (xs[SEQ - 1] != 0) ? (float)SEQ : (float)firstZero;

    if (tid < E4) {
        float4 acc = make_float4(0.f, 0.f, 0.f, 0.f);

        #pragma unroll 8
        for (int l = 0; l < SEQ; ++l) {
            const float4* row4 =
                reinterpret_cast<const float4*>(weight + (size_t)xs[l] * EDIM);
            const float4 v = __ldg(row4 + tid);
            acc.x += v.x; acc.y += v.y; acc.z += v.z; acc.w += v.w;
        }

        const float inv = 1.0f / len;
        acc.x *= inv; acc.y *= inv; acc.z *= inv; acc.w *= inv;
        reinterpret_cast<float4*>(g_y + (size_t)b * EDIM)[tid] = acc;
    }
}

// ---------------------------------------------------------------------------
// Kernel B: fused MLP.  h = relu(y @ w1^T + b1);  out = h @ w2^T + b2.
// 8 batch rows per block so w1 is read 128x (not 1024x). Each of 256 threads
// owns 2 hidden units across all 8 rows (16 accumulators), float4 loads.
// ---------------------------------------------------------------------------
#define ROWS 8

__global__ __launch_bounds__(256) void mlp_kernel(
    const float* __restrict__ w1,
    const float* __restrict__ b1,
    const float* __restrict__ w2,
    const float* __restrict__ b2,
    float* __restrict__ out)
{
    __shared__ __align__(16) float ys[ROWS][EDIM];  // 9.6 KB
    __shared__ float hs[ROWS][HDIM];                // 16 KB

    const int tid = threadIdx.x;
    const int b0  = blockIdx.x * ROWS;

    // stage the 8 pooled-embedding rows
    for (int i = tid; i < ROWS * EDIM; i += 256) {
        ys[i / EDIM][i % EDIM] = g_y[b0 * EDIM + i];
    }
    __syncthreads();

    // ---- GEMM1: each thread computes hidden units j0, j0+1 for all 8 rows
    const int j0 = tid * 2;
    float acc[ROWS][2];
    #pragma unroll
    for (int r = 0; r < ROWS; ++r) { acc[r][0] = 0.f; acc[r][1] = 0.f; }

    const float4* w1r0 = reinterpret_cast<const float4*>(w1 + (size_t)j0 * EDIM);
    const float4* w1r1 = reinterpret_cast<const float4*>(w1 + (size_t)(j0 + 1) * EDIM);

    #pragma unroll 5
    for (int e4 = 0; e4 < E4; ++e4) {
        const float4 wa = __ldg(w1r0 + e4);
        const float4 wb = __ldg(w1r1 + e4);
        #pragma unroll
        for (int r = 0; r < ROWS; ++r) {
            const float4 yv = *reinterpret_cast<const float4*>(&ys[r][e4 * 4]);
            acc[r][0] += yv.x * wa.x + yv.y * wa.y + yv.z * wa.z + yv.w * wa.w;
            acc[r][1] += yv.x * wb.x + yv.y * wb.y + yv.z * wb.z + yv.w * wb.w;
        }
    }

    const float bj0 = b1[j0];
    const float bj1 = b1[j0 + 1];
    #pragma unroll
    for (int r = 0; r < ROWS; ++r) {
        hs[r][j0]     = fmaxf(acc[r][0] + bj0, 0.f);
        hs[r][j0 + 1] = fmaxf(acc[r][1] + bj1, 0.f);
    }
    __syncthreads();

    // ---- GEMM2: warp r handles batch row r; 5 outputs via shfl reduction
    const int warp = tid >> 5;
    const int lane = tid & 31;
    if (warp < ROWS) {
        #pragma unroll
        for (int o = 0; o < ODIM; ++o) {
            float s = 0.f;
            #pragma unroll
            for (int k = lane; k < HDIM; k += 32)
                s += hs[warp][k] * __ldg(w2 + o * HDIM + k);
            #pragma unroll
            for (int off = 16; off > 0; off >>= 1)
                s += __shfl_down_sync(0xffffffffu, s, off);
            if (lane == 0)
                out[(b0 + warp) * ODIM + o] = s + b2[o];
        }
    }
}

// ---------------------------------------------------------------------------
extern "C" void kernel_launch(void* const* d_in, const int* in_sizes, int n_in,
                              void* d_out, int out_size)
{
    const int*   x      = (const int*)d_in[0];
    const float* weight = (const float*)d_in[1];
    const float* w1     = (const float*)d_in[2];
    const float* b1     = (const float*)d_in[3];
    const float* w2     = (const float*)d_in[4];
    const float* b2     = (const float*)d_in[5];
    float*       out    = (float*)d_out;

    gather_mean_kernel<<<BATCH, 96>>>(x, weight);
    mlp_kernel<<<BATCH / ROWS, 256>>>(w1, b1, w2, b2, out);
}